// round 1
// baseline (speedup 1.0000x reference)
#include <cuda_runtime.h>

#define NNEI 128
#define NG2  32
#define ND   32
#define NH   4
#define THREADS 128

#define ATTNW_SHIFT 20.0f
#define INV_SQRT_D  0.17677669529663687f   // 1/sqrt(32)
#define SQRT3       1.7320508075688772f

struct Smem {
    float wqkT[256][32];   // transposed w_qk: [j][c], j = d*8 + head_slot
    float wvT[128][32];    // transposed w_v:  [j][c], j = g*4 + h
    float wh[128][32];     // w_head natural [m][j]
    float K[128][36];      // K rows for current head (pad 36 for fl4 align)
    float V[128][36];      // V rows for current head
    float A[128 * 129];    // attention rows, pad 129 -> conflict-free
    float h2s[128][4];
    float sw[128];
    float swm[128];        // sw * mask
    float bh[32];
    float weq[4];
};

__device__ __forceinline__ float dot32(const float* a, const float* w) {
    const float4* w4 = reinterpret_cast<const float4*>(w);
    float s0 = 0.f, s1 = 0.f, s2 = 0.f, s3 = 0.f;
    float4 x0 = w4[0], x1 = w4[1], x2 = w4[2], x3 = w4[3];
    s0 = fmaf(a[0],  x0.x, s0); s0 = fmaf(a[1],  x0.y, s0);
    s0 = fmaf(a[2],  x0.z, s0); s0 = fmaf(a[3],  x0.w, s0);
    s1 = fmaf(a[4],  x1.x, s1); s1 = fmaf(a[5],  x1.y, s1);
    s1 = fmaf(a[6],  x1.z, s1); s1 = fmaf(a[7],  x1.w, s1);
    s2 = fmaf(a[8],  x2.x, s2); s2 = fmaf(a[9],  x2.y, s2);
    s2 = fmaf(a[10], x2.z, s2); s2 = fmaf(a[11], x2.w, s2);
    s3 = fmaf(a[12], x3.x, s3); s3 = fmaf(a[13], x3.y, s3);
    s3 = fmaf(a[14], x3.z, s3); s3 = fmaf(a[15], x3.w, s3);
    float4 y0 = w4[4], y1 = w4[5], y2 = w4[6], y3 = w4[7];
    s0 = fmaf(a[16], y0.x, s0); s0 = fmaf(a[17], y0.y, s0);
    s0 = fmaf(a[18], y0.z, s0); s0 = fmaf(a[19], y0.w, s0);
    s1 = fmaf(a[20], y1.x, s1); s1 = fmaf(a[21], y1.y, s1);
    s1 = fmaf(a[22], y1.z, s1); s1 = fmaf(a[23], y1.w, s1);
    s2 = fmaf(a[24], y2.x, s2); s2 = fmaf(a[25], y2.y, s2);
    s2 = fmaf(a[26], y2.z, s2); s2 = fmaf(a[27], y2.w, s2);
    s3 = fmaf(a[28], y3.x, s3); s3 = fmaf(a[29], y3.y, s3);
    s3 = fmaf(a[30], y3.z, s3); s3 = fmaf(a[31], y3.w, s3);
    return (s0 + s1) + (s2 + s3);
}

__global__ void __launch_bounds__(THREADS, 1)
repformer_kernel(const float* __restrict__ g2,
                 const float* __restrict__ h2,
                 const float* __restrict__ sw,
                 const float* __restrict__ wqk,
                 const float* __restrict__ wv,
                 const float* __restrict__ wh,
                 const float* __restrict__ bh,
                 const float* __restrict__ weq,
                 const int*   __restrict__ mask,
                 float* __restrict__ outg,
                 float* __restrict__ outh)
{
    extern __shared__ __align__(16) char smem_raw[];
    Smem& s = *reinterpret_cast<Smem*>(smem_raw);

    const int tid = threadIdx.x;
    const int loc = blockIdx.x;

    const float* g2l = g2 + (size_t)loc * NNEI * NG2;
    const float* h2l = h2 + (size_t)loc * NNEI * 3;
    const float* swl = sw + (size_t)loc * NNEI;
    const int*   ml  = mask + (size_t)loc * NNEI;

    // ---- stage weights / per-loc small tensors into smem ----
    for (int i = tid; i < 32 * 256; i += THREADS) s.wqkT[i & 255][i >> 8] = wqk[i];
    for (int i = tid; i < 32 * 128; i += THREADS) s.wvT[i & 127][i >> 7] = wv[i];
    for (int i = tid; i < 128 * 32; i += THREADS) (&s.wh[0][0])[i] = wh[i];
    for (int i = tid; i < NNEI * 3; i += THREADS) s.h2s[i / 3][i % 3] = h2l[i];
    {
        float sv = swl[tid];
        s.sw[tid] = sv;
        s.swm[tid] = ml[tid] ? sv : 0.0f;
    }
    if (tid < 32) s.bh[tid] = bh[tid];
    if (tid < 4)  s.weq[tid] = weq[tid];
    __syncthreads();

    // ---- per-thread row state ----
    float rg2[NG2];
    {
        const float4* gr = reinterpret_cast<const float4*>(g2l + (size_t)tid * NG2);
        #pragma unroll
        for (int i = 0; i < 8; ++i) {
            float4 v = gr[i];
            rg2[4 * i + 0] = v.x; rg2[4 * i + 1] = v.y;
            rg2[4 * i + 2] = v.z; rg2[4 * i + 3] = v.w;
        }
    }
    float rh2[3] = { s.h2s[tid][0], s.h2s[tid][1], s.h2s[tid][2] };
    const float rsw  = s.sw[tid];
    const float rswm = s.swm[tid];

    float g2o[NG2];
    #pragma unroll
    for (int j = 0; j < NG2; ++j) g2o[j] = s.bh[j];
    float och0 = 0.f, och1 = 0.f, och2 = 0.f;

    float* arow = &s.A[tid * 129];

    for (int h = 0; h < NH; ++h) {
        // ---- phase A: per-row Q(regs), K(smem), V(smem) for this head ----
        float rq[ND];
        #pragma unroll 4
        for (int d = 0; d < ND; ++d)
            rq[d] = dot32(rg2, s.wqkT[d * 8 + h]);
        #pragma unroll 4
        for (int d = 0; d < ND; ++d)
            s.K[tid][d] = dot32(rg2, s.wqkT[d * 8 + 4 + h]);
        #pragma unroll 4
        for (int g = 0; g < NG2; ++g)
            s.V[tid][g] = dot32(rg2, s.wvT[g * 4 + h]);
        __syncthreads();

        // ---- phase B: logits + rowmax ----
        float mx = -3.0e38f;
        #pragma unroll 2
        for (int k = 0; k < NNEI; ++k) {
            float dot = dot32(rq, s.K[k]);
            float h20 = s.h2s[k][0], h21 = s.h2s[k][1], h22 = s.h2s[k][2];
            float h2d = fmaf(rh2[0], h20, fmaf(rh2[1], h21, rh2[2] * h22));
            float lg = fmaf(dot * INV_SQRT_D * h2d + ATTNW_SHIFT,
                            rsw * s.sw[k], -ATTNW_SHIFT);
            mx = fmaxf(mx, lg);
            arow[k] = lg;
        }

        // ---- exp + sum (4 independent partial sums) ----
        float sm0 = 0.f, sm1 = 0.f, sm2 = 0.f, sm3 = 0.f;
        #pragma unroll 2
        for (int k = 0; k < NNEI; k += 4) {
            float e0 = __expf(arow[k + 0] - mx);
            float e1 = __expf(arow[k + 1] - mx);
            float e2 = __expf(arow[k + 2] - mx);
            float e3 = __expf(arow[k + 3] - mx);
            sm0 += e0; sm1 += e1; sm2 += e2; sm3 += e3;
            arow[k + 0] = e0; arow[k + 1] = e1;
            arow[k + 2] = e2; arow[k + 3] = e3;
        }
        float ssum = (sm0 + sm1) + (sm2 + sm3);
        float rowscale = rswm / (ssum * SQRT3);

        // ---- phase C: A @ V (32 cols) and A @ h2 (3 cols) ----
        float acc[NG2];
        #pragma unroll
        for (int g = 0; g < NG2; ++g) acc[g] = 0.f;
        float oh0 = 0.f, oh1 = 0.f, oh2 = 0.f;

        #pragma unroll 2
        for (int k = 0; k < NNEI; ++k) {
            float e = arow[k];
            float h20 = s.h2s[k][0], h21 = s.h2s[k][1], h22 = s.h2s[k][2];
            float h2d = fmaf(rh2[0], h20, fmaf(rh2[1], h21, rh2[2] * h22));
            float a = e * s.swm[k] * h2d * rowscale;
            const float4* vr = reinterpret_cast<const float4*>(s.V[k]);
            #pragma unroll
            for (int g4 = 0; g4 < 8; ++g4) {
                float4 v = vr[g4];
                acc[4 * g4 + 0] = fmaf(a, v.x, acc[4 * g4 + 0]);
                acc[4 * g4 + 1] = fmaf(a, v.y, acc[4 * g4 + 1]);
                acc[4 * g4 + 2] = fmaf(a, v.z, acc[4 * g4 + 2]);
                acc[4 * g4 + 3] = fmaf(a, v.w, acc[4 * g4 + 3]);
            }
            oh0 = fmaf(a, h20, oh0);
            oh1 = fmaf(a, h21, oh1);
            oh2 = fmaf(a, h22, oh2);
        }
        float weqh = s.weq[h];
        och0 = fmaf(weqh, oh0, och0);
        och1 = fmaf(weqh, oh1, och1);
        och2 = fmaf(weqh, oh2, och2);

        // ---- fold acc (out_g columns g*4+h) through w_head into g2o ----
        #pragma unroll 4
        for (int g = 0; g < NG2; ++g) {
            const float4* wr = reinterpret_cast<const float4*>(s.wh[g * 4 + h]);
            float ag = acc[g];
            #pragma unroll
            for (int j4 = 0; j4 < 8; ++j4) {
                float4 w = wr[j4];
                g2o[4 * j4 + 0] = fmaf(ag, w.x, g2o[4 * j4 + 0]);
                g2o[4 * j4 + 1] = fmaf(ag, w.y, g2o[4 * j4 + 1]);
                g2o[4 * j4 + 2] = fmaf(ag, w.z, g2o[4 * j4 + 2]);
                g2o[4 * j4 + 3] = fmaf(ag, w.w, g2o[4 * j4 + 3]);
            }
        }
        __syncthreads();   // guard K/V/A reuse by next head
    }

    // ---- write outputs ----
    float* go = outg + ((size_t)loc * NNEI + tid) * NG2;
    #pragma unroll
    for (int j4 = 0; j4 < 8; ++j4) {
        float4 v = make_float4(g2o[4 * j4 + 0], g2o[4 * j4 + 1],
                               g2o[4 * j4 + 2], g2o[4 * j4 + 3]);
        reinterpret_cast<float4*>(go)[j4] = v;
    }
    if (outh) {
        float* ho = outh + ((size_t)loc * NNEI + tid) * 3;
        ho[0] = och0; ho[1] = och1; ho[2] = och2;
    }
}

extern "C" void kernel_launch(void* const* d_in, const int* in_sizes, int n_in,
                              void* d_out, int out_size) {
    const float* g2  = (const float*)d_in[0];
    const float* h2  = (const float*)d_in[1];
    const float* sw  = (const float*)d_in[2];
    const float* wqk = (const float*)d_in[3];
    const float* wv  = (const float*)d_in[4];
    const float* wh  = (const float*)d_in[5];
    const float* bh  = (const float*)d_in[6];
    const float* weq = (const float*)d_in[7];
    const int*   msk = (const int*)d_in[8];

    int nloc = in_sizes[2] / NNEI;     // sw has nloc*nnei elements
    float* outg = (float*)d_out;
    // tuple output: g2_out then h2_out, concatenated. Guard in case only g2_out.
    size_t gsz = (size_t)nloc * NNEI * NG2;
    float* outh = ((size_t)out_size >= gsz + (size_t)nloc * NNEI * 3)
                      ? outg + gsz : nullptr;

    cudaFuncSetAttribute(repformer_kernel,
                         cudaFuncAttributeMaxDynamicSharedMemorySize,
                         (int)sizeof(Smem));
    repformer_kernel<<<nloc, THREADS, sizeof(Smem)>>>(
        g2, h2, sw, wqk, wv, wh, bh, weq, msk, outg, outh);
}